// round 8
// baseline (speedup 1.0000x reference)
#include <cuda_runtime.h>

// VectorQuantizer: inputs [32, 64, 64, 64] fp32 NCHW (C = D = 64), embedding [512, 64] fp32.
// Bit-exact replication of the reference fp32 arithmetic:
//   A   = sum_d fl(x_d * x_d)            (sequential mul-then-add chain, ascending d)
//   e2k = sum_d fl(e_d * e_d)            (sequential mul-then-add chain, ascending d)
//   s_k = FMA-chain_d (x_d * e_dk)       (ascending d, single accumulator)
//   dist_k = fl( fl(A + e2k) + fl(-2*s_k) )
//   argmin: first-occurrence. Streaming fminf per 32-code chunk -> (best, chunk) in regs;
//           winning chunk recomputed bit-exactly at the end, first-j equality match.
//   out = fl(x + fl(q - x))              (exact straight-through-estimator rounding)
//
// Perf: 2 pixels/thread share every codebook LDS.128; chunk=32 amortizes pack MOVs;
// no argmin arrays -> lower reg peak -> deeper LDS pipelining.

#define NUM_CODES 512
#define DIMS      64
#define TPB       256
#define NPIX      (32 * 64 * 64)          // 131072 pixels
#define NPAIRS    (NPIX / 2)              // 65536: pair (n, n+NPAIRS)
#define IMG_STRIDE (64 * 4096)            // floats per image (C*H*W)
#define PAIR_OFF  (16 * IMG_STRIDE)       // pixel n+65536 is image b+16, same (h,w)
#define CHUNK     32
#define SMEM_FLOATS (DIMS * NUM_CODES + NUM_CODES)
#define SMEM_BYTES  (SMEM_FLOATS * 4)     // 133120 bytes
#define GRID 152

typedef unsigned long long ull;

__device__ __forceinline__ ull ffma2(ull a, ull b, ull c) {
    ull d;
    asm("fma.rn.f32x2 %0, %1, %2, %3;" : "=l"(d) : "l"(a), "l"(b), "l"(c));
    return d;
}
__device__ __forceinline__ ull fadd2(ull a, ull b) {
    ull d;
    asm("add.rn.f32x2 %0, %1, %2;" : "=l"(d) : "l"(a), "l"(b));
    return d;
}
__device__ __forceinline__ ull fmul2(ull a, ull b) {
    ull d;
    asm("mul.rn.f32x2 %0, %1, %2;" : "=l"(d) : "l"(a), "l"(b));
    return d;
}
__device__ __forceinline__ ull pack2(float x) {
    ull r;
    asm("mov.b64 %0, {%1, %1};" : "=l"(r) : "f"(x));
    return r;
}
__device__ __forceinline__ void unpack2(ull v, float& lo, float& hi) {
    asm("mov.b64 {%0, %1}, %2;" : "=f"(lo), "=f"(hi) : "l"(v));
}

// Bit-exact distances for one 32-code chunk (same op order as the main sweep).
__device__ __forceinline__ void chunk_dists(const float* __restrict__ x, ull Ap, ull neg2,
                                            const float* __restrict__ Es,
                                            const float* __restrict__ e2s,
                                            int k0, float* __restrict__ dist) {
    ull acc[16];
    #pragma unroll
    for (int j = 0; j < 16; ++j) acc[j] = 0ull;
    #pragma unroll 8
    for (int d = 0; d < DIMS; ++d) {
        const ull xp = pack2(x[d]);
        const ulonglong2* p = reinterpret_cast<const ulonglong2*>(Es + d * NUM_CODES + k0);
        #pragma unroll
        for (int q = 0; q < 8; ++q) {
            ulonglong2 e = p[q];
            acc[2 * q]     = ffma2(xp, e.x, acc[2 * q]);
            acc[2 * q + 1] = ffma2(xp, e.y, acc[2 * q + 1]);
        }
    }
    const ull* e2q = reinterpret_cast<const ull*>(e2s + k0);
    #pragma unroll
    for (int j = 0; j < 16; ++j) {
        const ull dd = fadd2(fadd2(Ap, e2q[j]), fmul2(neg2, acc[j]));
        unpack2(dd, dist[2 * j], dist[2 * j + 1]);
    }
}

__global__ __launch_bounds__(TPB, 1)
void vq_kernel(const float* __restrict__ in,
               const float* __restrict__ emb,
               float* __restrict__ out) {
    extern __shared__ float smem[];
    float* Es  = smem;                      // transposed codebook [DIMS][NUM_CODES]
    float* e2s = smem + DIMS * NUM_CODES;   // ||e_k||^2, [NUM_CODES]

    const int tid = threadIdx.x;

    // ---- Stage codebook into smem, transposed, + sequential-chain squared norms ----
    #pragma unroll
    for (int kk = 0; kk < 2; ++kk) {
        const int k = tid + kk * TPB;
        const float4* row = reinterpret_cast<const float4*>(emb + k * DIMS);
        float s = 0.0f;
        #pragma unroll
        for (int j = 0; j < DIMS / 4; ++j) {
            float4 v = row[j];
            Es[(4 * j + 0) * NUM_CODES + k] = v.x;
            Es[(4 * j + 1) * NUM_CODES + k] = v.y;
            Es[(4 * j + 2) * NUM_CODES + k] = v.z;
            Es[(4 * j + 3) * NUM_CODES + k] = v.w;
            s = __fadd_rn(s, __fmul_rn(v.x, v.x));
            s = __fadd_rn(s, __fmul_rn(v.y, v.y));
            s = __fadd_rn(s, __fmul_rn(v.z, v.z));
            s = __fadd_rn(s, __fmul_rn(v.w, v.w));
        }
        e2s[k] = s;
    }
    __syncthreads();

    const ull neg2 = pack2(-2.0f);
    const int totalThreads = GRID * TPB;

    for (int p = blockIdx.x * TPB + tid; p < NPAIRS; p += totalThreads) {
        const int base0 = ((p >> 12) * IMG_STRIDE) + (p & 4095);
        const float* px0 = in + base0;
        const float* px1 = in + base0 + PAIR_OFF;

        float x0[DIMS], x1[DIMS];
        #pragma unroll
        for (int d = 0; d < DIMS; ++d) x0[d] = px0[d << 12];
        #pragma unroll
        for (int d = 0; d < DIMS; ++d) x1[d] = px1[d << 12];

        // A = ||x||^2 : strict sequential mul-then-add chain, ascending d.
        float A0 = 0.0f, A1 = 0.0f;
        #pragma unroll
        for (int d = 0; d < DIMS; ++d) A0 = __fadd_rn(A0, __fmul_rn(x0[d], x0[d]));
        #pragma unroll
        for (int d = 0; d < DIMS; ++d) A1 = __fadd_rn(A1, __fmul_rn(x1[d], x1[d]));
        const ull A0p = pack2(A0);
        const ull A1p = pack2(A1);

        float best0 = 3.402823466e+38f, best1 = 3.402823466e+38f;
        int   bc0 = 0, bc1 = 0;

        // ---- Main sweep: 16 chunks of 32 codes ----
        #pragma unroll 1
        for (int k0 = 0; k0 < NUM_CODES; k0 += CHUNK) {
            ull acc0[16], acc1[16];
            #pragma unroll
            for (int j = 0; j < 16; ++j) { acc0[j] = 0ull; acc1[j] = 0ull; }

            // s_k: single-accumulator FMA chain over d ascending (per f32x2 lane).
            // One set of codebook loads feeds BOTH pixels; 2 pack-MOVs per d cover 32 FFMA2.
            #pragma unroll 8
            for (int d = 0; d < DIMS; ++d) {
                const ull xp0 = pack2(x0[d]);
                const ull xp1 = pack2(x1[d]);
                const ulonglong2* ptr =
                    reinterpret_cast<const ulonglong2*>(Es + d * NUM_CODES + k0);
                #pragma unroll
                for (int q = 0; q < 8; ++q) {
                    ulonglong2 e = ptr[q];
                    acc0[2 * q]     = ffma2(xp0, e.x, acc0[2 * q]);
                    acc1[2 * q]     = ffma2(xp1, e.x, acc1[2 * q]);
                    acc0[2 * q + 1] = ffma2(xp0, e.y, acc0[2 * q + 1]);
                    acc1[2 * q + 1] = ffma2(xp1, e.y, acc1[2 * q + 1]);
                }
            }

            // Streaming finalize: dist = fl( fl(A+e2k) + fl(-2*s) ), fold min (no arrays).
            const ull* e2q = reinterpret_cast<const ull*>(e2s + k0);
            float m0 = 3.402823466e+38f, m1 = 3.402823466e+38f;
            #pragma unroll
            for (int j = 0; j < 16; ++j) {
                const ull e2j = e2q[j];
                const ull d0 = fadd2(fadd2(A0p, e2j), fmul2(neg2, acc0[j]));
                const ull d1 = fadd2(fadd2(A1p, e2j), fmul2(neg2, acc1[j]));
                float l0, h0, l1, h1;
                unpack2(d0, l0, h0);
                unpack2(d1, l1, h1);
                m0 = fminf(m0, fminf(l0, h0));
                m1 = fminf(m1, fminf(l1, h1));
            }
            const int c = k0 >> 5;
            if (m0 < best0) { best0 = m0; bc0 = c; }   // strict < : earliest chunk wins
            if (m1 < best1) { best1 = m1; bc1 = c; }
        }

        // ---- Recompute winning chunk bit-exactly; first j with dist==best ----
        float dist[CHUNK];
        int bestk0, bestk1;

        chunk_dists(x0, A0p, neg2, Es, e2s, bc0 * CHUNK, dist);
        {
            int bj = 0;
            #pragma unroll
            for (int j = CHUNK - 1; j >= 0; --j) if (dist[j] == best0) bj = j; // smallest j
            bestk0 = bc0 * CHUNK + bj;
        }
        chunk_dists(x1, A1p, neg2, Es, e2s, bc1 * CHUNK, dist);
        {
            int bj = 0;
            #pragma unroll
            for (int j = CHUNK - 1; j >= 0; --j) if (dist[j] == best1) bj = j;
            bestk1 = bc1 * CHUNK + bj;
        }

        // ---- Write back with exact STE rounding: out = fl(x + fl(q - x)) ----
        float* po0 = out + base0;
        float* po1 = out + base0 + PAIR_OFF;
        #pragma unroll
        for (int d = 0; d < DIMS; ++d) {
            const float q0v = Es[d * NUM_CODES + bestk0];
            const float q1v = Es[d * NUM_CODES + bestk1];
            po0[d << 12] = __fadd_rn(x0[d], __fsub_rn(q0v, x0[d]));
            po1[d << 12] = __fadd_rn(x1[d], __fsub_rn(q1v, x1[d]));
        }
    }
}

extern "C" void kernel_launch(void* const* d_in, const int* in_sizes, int n_in,
                              void* d_out, int out_size) {
    const float* in  = (const float*)d_in[0];   // inputs  [32,64,64,64] fp32
    const float* emb = (const float*)d_in[1];   // embedding [512,64] fp32
    float* out = (float*)d_out;

    cudaFuncSetAttribute(vq_kernel, cudaFuncAttributeMaxDynamicSharedMemorySize, SMEM_BYTES);
    vq_kernel<<<GRID, TPB, SMEM_BYTES>>>(in, emb, out);
}

// round 9
// speedup vs baseline: 1.7458x; 1.7458x over previous
#include <cuda_runtime.h>

// VectorQuantizer: inputs [32, 64, 64, 64] fp32 NCHW (C = D = 64), embedding [512, 64] fp32.
// Bit-exact replication of the reference fp32 arithmetic:
//   A   = sum_d fl(x_d * x_d)            (sequential mul-then-add chain, ascending d)
//   e2k = sum_d fl(e_d * e_d)            (sequential mul-then-add chain, ascending d)
//   s_k = FMA-chain_d (x_d * e_dk)       (ascending d, single accumulator)
//   dist_k = fl( fl(A + e2k) + fl(-2*s_k) )
//   argmin: first-occurrence. Streaming fminf per 16-code chunk -> (best, chunk) in regs;
//           winning chunk recomputed bit-exactly at the end, ascending-j equality match.
//   out = fl(x + fl(q - x))              (exact straight-through-estimator rounding)
//
// Perf notes (R4-R8 evidence): peak live regs in the d-loop is the controlling resource.
// CHUNK=16 (acc=32 regs) + 2 pixels/thread sharing every broadcast LDS.128; argmin
// bookkeeping is register-light streaming min, no arrays, no smem spill.

#define NUM_CODES 512
#define DIMS      64
#define TPB       256
#define NPIX      (32 * 64 * 64)          // 131072 pixels
#define NPAIRS    (NPIX / 2)              // 65536: pair (n, n+NPAIRS)
#define IMG_STRIDE (64 * 4096)            // floats per image (C*H*W)
#define PAIR_OFF  (16 * IMG_STRIDE)       // pixel n+65536 is image b+16, same (h,w)
#define CHUNK     16
#define SMEM_FLOATS (DIMS * NUM_CODES + NUM_CODES)
#define SMEM_BYTES  (SMEM_FLOATS * 4)     // 133120 bytes
#define GRID 152

typedef unsigned long long ull;

__device__ __forceinline__ ull ffma2(ull a, ull b, ull c) {
    ull d;
    asm("fma.rn.f32x2 %0, %1, %2, %3;" : "=l"(d) : "l"(a), "l"(b), "l"(c));
    return d;
}
__device__ __forceinline__ ull fadd2(ull a, ull b) {
    ull d;
    asm("add.rn.f32x2 %0, %1, %2;" : "=l"(d) : "l"(a), "l"(b));
    return d;
}
__device__ __forceinline__ ull fmul2(ull a, ull b) {
    ull d;
    asm("mul.rn.f32x2 %0, %1, %2;" : "=l"(d) : "l"(a), "l"(b));
    return d;
}
__device__ __forceinline__ ull pack2(float x) {
    ull r;
    asm("mov.b64 %0, {%1, %1};" : "=l"(r) : "f"(x));
    return r;
}
__device__ __forceinline__ void unpack2(ull v, float& lo, float& hi) {
    asm("mov.b64 {%0, %1}, %2;" : "=f"(lo), "=f"(hi) : "l"(v));
}

// Bit-exact distances for one 16-code chunk (same op order as the main sweep).
__device__ __forceinline__ void chunk_dists(const float* __restrict__ x, ull Ap, ull neg2,
                                            const float* __restrict__ Es,
                                            const float* __restrict__ e2s,
                                            int k0, float* __restrict__ dist) {
    ull acc[8];
    #pragma unroll
    for (int j = 0; j < 8; ++j) acc[j] = 0ull;
    #pragma unroll
    for (int d = 0; d < DIMS; ++d) {
        const ull xp = pack2(x[d]);
        const ulonglong2* p = reinterpret_cast<const ulonglong2*>(Es + d * NUM_CODES + k0);
        ulonglong2 q0 = p[0], q1 = p[1], q2 = p[2], q3 = p[3];
        acc[0] = ffma2(xp, q0.x, acc[0]);
        acc[1] = ffma2(xp, q0.y, acc[1]);
        acc[2] = ffma2(xp, q1.x, acc[2]);
        acc[3] = ffma2(xp, q1.y, acc[3]);
        acc[4] = ffma2(xp, q2.x, acc[4]);
        acc[5] = ffma2(xp, q2.y, acc[5]);
        acc[6] = ffma2(xp, q3.x, acc[6]);
        acc[7] = ffma2(xp, q3.y, acc[7]);
    }
    const ull* e2q = reinterpret_cast<const ull*>(e2s + k0);
    #pragma unroll
    for (int j = 0; j < 8; ++j) {
        const ull dd = fadd2(fadd2(Ap, e2q[j]), fmul2(neg2, acc[j]));
        unpack2(dd, dist[2 * j], dist[2 * j + 1]);
    }
}

__global__ __launch_bounds__(TPB, 1)
void vq_kernel(const float* __restrict__ in,
               const float* __restrict__ emb,
               float* __restrict__ out) {
    extern __shared__ float smem[];
    float* Es  = smem;                      // transposed codebook [DIMS][NUM_CODES]
    float* e2s = smem + DIMS * NUM_CODES;   // ||e_k||^2, [NUM_CODES]

    const int tid = threadIdx.x;

    // ---- Stage codebook into smem, transposed, + sequential-chain squared norms ----
    #pragma unroll
    for (int kk = 0; kk < 2; ++kk) {
        const int k = tid + kk * TPB;
        const float4* row = reinterpret_cast<const float4*>(emb + k * DIMS);
        float s = 0.0f;
        #pragma unroll
        for (int j = 0; j < DIMS / 4; ++j) {
            float4 v = row[j];
            Es[(4 * j + 0) * NUM_CODES + k] = v.x;
            Es[(4 * j + 1) * NUM_CODES + k] = v.y;
            Es[(4 * j + 2) * NUM_CODES + k] = v.z;
            Es[(4 * j + 3) * NUM_CODES + k] = v.w;
            s = __fadd_rn(s, __fmul_rn(v.x, v.x));
            s = __fadd_rn(s, __fmul_rn(v.y, v.y));
            s = __fadd_rn(s, __fmul_rn(v.z, v.z));
            s = __fadd_rn(s, __fmul_rn(v.w, v.w));
        }
        e2s[k] = s;
    }
    __syncthreads();

    const ull neg2 = pack2(-2.0f);
    const int totalThreads = GRID * TPB;

    for (int p = blockIdx.x * TPB + tid; p < NPAIRS; p += totalThreads) {
        const int base0 = ((p >> 12) * IMG_STRIDE) + (p & 4095);
        const float* px0 = in + base0;
        const float* px1 = in + base0 + PAIR_OFF;

        float x0[DIMS], x1[DIMS];
        #pragma unroll
        for (int d = 0; d < DIMS; ++d) x0[d] = px0[d << 12];
        #pragma unroll
        for (int d = 0; d < DIMS; ++d) x1[d] = px1[d << 12];

        // A = ||x||^2 : strict sequential mul-then-add chain, ascending d.
        float A0 = 0.0f, A1 = 0.0f;
        #pragma unroll
        for (int d = 0; d < DIMS; ++d) A0 = __fadd_rn(A0, __fmul_rn(x0[d], x0[d]));
        #pragma unroll
        for (int d = 0; d < DIMS; ++d) A1 = __fadd_rn(A1, __fmul_rn(x1[d], x1[d]));
        const ull A0p = pack2(A0);
        const ull A1p = pack2(A1);

        float best0 = 3.402823466e+38f, best1 = 3.402823466e+38f;
        int   bc0 = 0, bc1 = 0;

        // ---- Main sweep: 32 chunks of 16 codes ----
        #pragma unroll 1
        for (int k0 = 0; k0 < NUM_CODES; k0 += CHUNK) {
            ull acc0[8], acc1[8];
            #pragma unroll
            for (int j = 0; j < 8; ++j) { acc0[j] = 0ull; acc1[j] = 0ull; }

            // s_k: single-accumulator FMA chain over d ascending (per f32x2 lane).
            // One set of codebook loads feeds BOTH pixels.
            #pragma unroll
            for (int d = 0; d < DIMS; ++d) {
                const ull xp0 = pack2(x0[d]);
                const ull xp1 = pack2(x1[d]);
                const ulonglong2* ptr =
                    reinterpret_cast<const ulonglong2*>(Es + d * NUM_CODES + k0);
                ulonglong2 q0 = ptr[0];
                ulonglong2 q1 = ptr[1];
                ulonglong2 q2 = ptr[2];
                ulonglong2 q3 = ptr[3];
                acc0[0] = ffma2(xp0, q0.x, acc0[0]);  acc1[0] = ffma2(xp1, q0.x, acc1[0]);
                acc0[1] = ffma2(xp0, q0.y, acc0[1]);  acc1[1] = ffma2(xp1, q0.y, acc1[1]);
                acc0[2] = ffma2(xp0, q1.x, acc0[2]);  acc1[2] = ffma2(xp1, q1.x, acc1[2]);
                acc0[3] = ffma2(xp0, q1.y, acc0[3]);  acc1[3] = ffma2(xp1, q1.y, acc1[3]);
                acc0[4] = ffma2(xp0, q2.x, acc0[4]);  acc1[4] = ffma2(xp1, q2.x, acc1[4]);
                acc0[5] = ffma2(xp0, q2.y, acc0[5]);  acc1[5] = ffma2(xp1, q2.y, acc1[5]);
                acc0[6] = ffma2(xp0, q3.x, acc0[6]);  acc1[6] = ffma2(xp1, q3.x, acc1[6]);
                acc0[7] = ffma2(xp0, q3.y, acc0[7]);  acc1[7] = ffma2(xp1, q3.y, acc1[7]);
            }

            // Streaming finalize: dist = fl( fl(A+e2k) + fl(-2*s) ); fold min, no arrays.
            const ull* e2q = reinterpret_cast<const ull*>(e2s + k0);
            float m0 = 3.402823466e+38f, m1 = 3.402823466e+38f;
            #pragma unroll
            for (int j = 0; j < 8; ++j) {
                const ull e2j = e2q[j];
                const ull d0 = fadd2(fadd2(A0p, e2j), fmul2(neg2, acc0[j]));
                const ull d1 = fadd2(fadd2(A1p, e2j), fmul2(neg2, acc1[j]));
                float l0, h0, l1, h1;
                unpack2(d0, l0, h0);
                unpack2(d1, l1, h1);
                m0 = fminf(m0, fminf(l0, h0));
                m1 = fminf(m1, fminf(l1, h1));
            }
            const int c = k0 >> 4;
            if (m0 < best0) { best0 = m0; bc0 = c; }   // strict < : earliest chunk wins
            if (m1 < best1) { best1 = m1; bc1 = c; }
        }

        // ---- Recompute winning chunk bit-exactly; first j with dist==best ----
        float dist[CHUNK];
        int bestk0, bestk1;

        chunk_dists(x0, A0p, neg2, Es, e2s, bc0 * CHUNK, dist);
        {
            int bj = 0;
            #pragma unroll
            for (int j = CHUNK - 1; j >= 0; --j) if (dist[j] == best0) bj = j; // smallest j
            bestk0 = bc0 * CHUNK + bj;
        }
        chunk_dists(x1, A1p, neg2, Es, e2s, bc1 * CHUNK, dist);
        {
            int bj = 0;
            #pragma unroll
            for (int j = CHUNK - 1; j >= 0; --j) if (dist[j] == best1) bj = j;
            bestk1 = bc1 * CHUNK + bj;
        }

        // ---- Write back with exact STE rounding: out = fl(x + fl(q - x)) ----
        float* po0 = out + base0;
        float* po1 = out + base0 + PAIR_OFF;
        #pragma unroll
        for (int d = 0; d < DIMS; ++d) {
            const float q0v = Es[d * NUM_CODES + bestk0];
            const float q1v = Es[d * NUM_CODES + bestk1];
            po0[d << 12] = __fadd_rn(x0[d], __fsub_rn(q0v, x0[d]));
            po1[d << 12] = __fadd_rn(x1[d], __fsub_rn(q1v, x1[d]));
        }
    }
}

extern "C" void kernel_launch(void* const* d_in, const int* in_sizes, int n_in,
                              void* d_out, int out_size) {
    const float* in  = (const float*)d_in[0];   // inputs  [32,64,64,64] fp32
    const float* emb = (const float*)d_in[1];   // embedding [512,64] fp32
    float* out = (float*)d_out;

    cudaFuncSetAttribute(vq_kernel, cudaFuncAttributeMaxDynamicSharedMemorySize, SMEM_BYTES);
    vq_kernel<<<GRID, TPB, SMEM_BYTES>>>(in, emb, out);
}

// round 11
// speedup vs baseline: 2.5261x; 1.4469x over previous
#include <cuda_runtime.h>

// VectorQuantizer: inputs [32, 64, 64, 64] fp32 NCHW (C = D = 64), embedding [512, 64] fp32.
// Bit-exact replication of the reference fp32 arithmetic:
//   A   = sum_d fl(x_d * x_d)            (sequential mul-then-add chain, ascending d)
//   e2k = sum_d fl(e_d * e_d)            (sequential mul-then-add chain, ascending d)
//   s_k = FMA-chain_d (x_d * e_dk)       (ascending d, single accumulator per code)
//   dist_k = fl( fl(A + e2k) + fl(-2*s_k) )
//   argmin: first-occurrence via u64 key = fp32bits(dist)<<32 | k (dist>0 -> monotone),
//           lane-local fold + warp butterfly min.
//   out = fl(x + fl(q - x))              (exact straight-through-estimator rounding)
//
// Layout (R9 lesson: lane-private-pixel layout is register-walled at 2 px reuse):
//   lanes own CODES (stride-1 LDS.128 codebook), pixels staged in smem (x uses 0 regs),
//   P=8 pixels per warp-iteration share every codebook load.

#define NUM_CODES 512
#define DIMS      64
#define TPB       256
#define NPIX      (32 * 64 * 64)          // 131072 pixels
#define IMG_STRIDE (64 * 4096)
#define TILE      128                      // pixels per CTA pass
#define NTILES    (NPIX / TILE)            // 1024
#define GRID      152

// smem layout (floats)
#define ES_OFF   0                          // Es[d][k]      64*512
#define E2_OFF   (DIMS * NUM_CODES)         // e2s[k]        512
#define XS_OFF   (E2_OFF + NUM_CODES)       // xs[d][px]     64*128
#define AS_OFF   (XS_OFF + DIMS * TILE)     // A[px]         128
#define WIN_OFF  (AS_OFF + TILE)            // win[px]       128 (as uint)
#define SMEM_FLOATS (WIN_OFF + TILE)
#define SMEM_BYTES  (SMEM_FLOATS * 4)       // 166912 bytes

typedef unsigned long long ull;

__device__ __forceinline__ ull ffma2(ull a, ull b, ull c) {
    ull d;
    asm("fma.rn.f32x2 %0, %1, %2, %3;" : "=l"(d) : "l"(a), "l"(b), "l"(c));
    return d;
}
__device__ __forceinline__ ull fadd2(ull a, ull b) {
    ull d;
    asm("add.rn.f32x2 %0, %1, %2;" : "=l"(d) : "l"(a), "l"(b));
    return d;
}
__device__ __forceinline__ ull fmul2(ull a, ull b) {
    ull d;
    asm("mul.rn.f32x2 %0, %1, %2;" : "=l"(d) : "l"(a), "l"(b));
    return d;
}
__device__ __forceinline__ ull pack2(float x) {
    ull r;
    asm("mov.b64 %0, {%1, %1};" : "=l"(r) : "f"(x));
    return r;
}
__device__ __forceinline__ void unpack2(ull v, float& lo, float& hi) {
    asm("mov.b64 {%0, %1}, %2;" : "=f"(lo), "=f"(hi) : "l"(v));
}
__device__ __forceinline__ ull umin64(ull a, ull b) { return a < b ? a : b; }

__global__ __launch_bounds__(TPB, 1)
void vq_kernel(const float* __restrict__ in,
               const float* __restrict__ emb,
               float* __restrict__ out) {
    extern __shared__ float smem[];
    float* Es  = smem + ES_OFF;             // transposed codebook [DIMS][NUM_CODES]
    float* e2s = smem + E2_OFF;             // ||e_k||^2
    float* xs  = smem + XS_OFF;             // x tile [DIMS][TILE]
    float* As  = smem + AS_OFF;             // ||x||^2 per pixel
    unsigned* win = reinterpret_cast<unsigned*>(smem + WIN_OFF);

    const int tid  = threadIdx.x;
    const int lane = tid & 31;
    const int w    = tid >> 5;

    // ---- Stage codebook into smem, transposed, + sequential-chain squared norms ----
    #pragma unroll
    for (int kk = 0; kk < 2; ++kk) {
        const int k = tid + kk * TPB;
        const float4* row = reinterpret_cast<const float4*>(emb + k * DIMS);
        float s = 0.0f;
        #pragma unroll
        for (int j = 0; j < DIMS / 4; ++j) {
            float4 v = row[j];
            Es[(4 * j + 0) * NUM_CODES + k] = v.x;
            Es[(4 * j + 1) * NUM_CODES + k] = v.y;
            Es[(4 * j + 2) * NUM_CODES + k] = v.z;
            Es[(4 * j + 3) * NUM_CODES + k] = v.w;
            s = __fadd_rn(s, __fmul_rn(v.x, v.x));
            s = __fadd_rn(s, __fmul_rn(v.y, v.y));
            s = __fadd_rn(s, __fmul_rn(v.z, v.z));
            s = __fadd_rn(s, __fmul_rn(v.w, v.w));
        }
        e2s[k] = s;
    }
    __syncthreads();

    const ull neg2 = pack2(-2.0f);

    for (int tile = blockIdx.x; tile < NTILES; tile += GRID) {
        // pixels px = tile*128 + i; (px>>12) constant per tile since TILE=128 | 4096
        const int tileBase = (tile >> 5) * IMG_STRIDE + (tile & 31) * TILE;

        // ---- Stage x tile: thread (i = tid&127, h = tid>>7) loads 32 dims, coalesced ----
        {
            const int i = tid & 127;
            const int h = tid >> 7;
            const float* px = in + tileBase + i;
            #pragma unroll
            for (int j = 0; j < 32; ++j) {
                const int d = h * 32 + j;
                xs[d * TILE + i] = px[(size_t)d << 12];
            }
        }
        __syncthreads();

        // ---- A = ||x||^2 per pixel: strict sequential chain ascending d ----
        if (tid < TILE) {
            float A = 0.0f;
            #pragma unroll
            for (int d = 0; d < DIMS; ++d) {
                const float v = xs[d * TILE + tid];
                A = __fadd_rn(A, __fmul_rn(v, v));
            }
            As[tid] = A;
        }
        __syncthreads();

        // ---- Compute: warp w handles px [w*16, w*16+16), in two blocks of P=8 ----
        // lane owns codes k = c*128 + lane*4 + {0..3}, c = 0..3 (16 codes -> 8 f32x2 acc/px)
        #pragma unroll 1
        for (int halfI = 0; halfI < 2; ++halfI) {
            const int p0 = w * 16 + halfI * 8;

            ull acc[8][8];
            #pragma unroll
            for (int p = 0; p < 8; ++p)
                #pragma unroll
                for (int j = 0; j < 8; ++j) acc[p][j] = 0ull;

            #pragma unroll 4
            for (int d = 0; d < DIMS; ++d) {
                const float* xrow = xs + d * TILE + p0;
                const float4 xa = *reinterpret_cast<const float4*>(xrow);
                const float4 xb = *reinterpret_cast<const float4*>(xrow + 4);
                ull xq[8];
                xq[0] = pack2(xa.x); xq[1] = pack2(xa.y);
                xq[2] = pack2(xa.z); xq[3] = pack2(xa.w);
                xq[4] = pack2(xb.x); xq[5] = pack2(xb.y);
                xq[6] = pack2(xb.z); xq[7] = pack2(xb.w);

                const float* erow = Es + d * NUM_CODES + lane * 4;
                const ulonglong2 E0 = *reinterpret_cast<const ulonglong2*>(erow);
                const ulonglong2 E1 = *reinterpret_cast<const ulonglong2*>(erow + 128);
                const ulonglong2 E2 = *reinterpret_cast<const ulonglong2*>(erow + 256);
                const ulonglong2 E3 = *reinterpret_cast<const ulonglong2*>(erow + 384);

                #pragma unroll
                for (int p = 0; p < 8; ++p) {
                    const ull xp = xq[p];
                    acc[p][0] = ffma2(xp, E0.x, acc[p][0]);
                    acc[p][1] = ffma2(xp, E0.y, acc[p][1]);
                    acc[p][2] = ffma2(xp, E1.x, acc[p][2]);
                    acc[p][3] = ffma2(xp, E1.y, acc[p][3]);
                    acc[p][4] = ffma2(xp, E2.x, acc[p][4]);
                    acc[p][5] = ffma2(xp, E2.y, acc[p][5]);
                    acc[p][6] = ffma2(xp, E3.x, acc[p][6]);
                    acc[p][7] = ffma2(xp, E3.y, acc[p][7]);
                }
            }

            // e2 pairs for this lane's codes (shared across the 8 pixels)
            ull e2p[8];
            {
                const float* e2row = e2s + lane * 4;
                #pragma unroll
                for (int c = 0; c < 4; ++c) {
                    const ulonglong2 t =
                        *reinterpret_cast<const ulonglong2*>(e2row + c * 128);
                    e2p[2 * c]     = t.x;
                    e2p[2 * c + 1] = t.y;
                }
            }

            // Finalize per pixel: dist = fl( fl(A+e2) + fl(-2*s) ); u64-key argmin.
            #pragma unroll
            for (int p = 0; p < 8; ++p) {
                const ull Ap = pack2(As[p0 + p]);
                ull key[16];
                #pragma unroll
                for (int j = 0; j < 8; ++j) {
                    const ull dd = fadd2(fadd2(Ap, e2p[j]), fmul2(neg2, acc[p][j]));
                    float lo, hi;
                    unpack2(dd, lo, hi);
                    const unsigned kb = (unsigned)((j >> 1) * 128 + lane * 4 + (j & 1) * 2);
                    key[2 * j]     = ((ull)__float_as_uint(lo) << 32) | kb;
                    key[2 * j + 1] = ((ull)__float_as_uint(hi) << 32) | (kb + 1);
                }
                #pragma unroll
                for (int stride = 8; stride >= 1; stride >>= 1)
                    #pragma unroll
                    for (int j = 0; j < stride; ++j)
                        key[j] = umin64(key[j], key[j + stride]);

                ull best = key[0];
                #pragma unroll
                for (int m = 16; m >= 1; m >>= 1) {
                    const ull other = __shfl_xor_sync(0xFFFFFFFFu, best, m);
                    best = umin64(best, other);
                }
                if (lane == 0) win[p0 + p] = (unsigned)best;
            }
        }
        __syncthreads();

        // ---- STE write: thread (i, h) writes 32 dims of pixel i, coalesced ----
        {
            const int i = tid & 127;
            const int h = tid >> 7;
            const unsigned k = win[i];
            float* po = out + tileBase + i;
            #pragma unroll
            for (int j = 0; j < 32; ++j) {
                const int d = h * 32 + j;
                const float xv = xs[d * TILE + i];
                const float qv = Es[d * NUM_CODES + (int)k];
                po[(size_t)d << 12] = __fadd_rn(xv, __fsub_rn(qv, xv));
            }
        }
        __syncthreads();   // protect xs/win before next tile overwrites
    }
}

extern "C" void kernel_launch(void* const* d_in, const int* in_sizes, int n_in,
                              void* d_out, int out_size) {
    const float* in  = (const float*)d_in[0];   // inputs  [32,64,64,64] fp32
    const float* emb = (const float*)d_in[1];   // embedding [512,64] fp32
    float* out = (float*)d_out;

    cudaFuncSetAttribute(vq_kernel, cudaFuncAttributeMaxDynamicSharedMemorySize, SMEM_BYTES);
    vq_kernel<<<GRID, TPB, SMEM_BYTES>>>(in, emb, out);
}